// round 1
// baseline (speedup 1.0000x reference)
#include <cuda_runtime.h>
#include <math.h>
#include <stdint.h>

#define BATCH 8
#define LSEQ 512
#define DMODEL 1024
#define NH 16
#define DK 64

// ---------------- scratch (static device memory; no allocations) ----------------
__device__ float g_Q[BATCH * NH * LSEQ * DK];     // [B,H,L,DK]
__device__ float g_K[BATCH * NH * LSEQ * DK];
__device__ float g_V[BATCH * NH * LSEQ * DK];
__device__ float g_CTX[BATCH * LSEQ * DMODEL];    // [B*L, D] heads merged
__device__ float g_P[3][BATCH * LSEQ * LSEQ];     // cumulative distance products P1,P2,P3
__device__ float g_QP[4][BATCH * LSEQ];           // qp positions, t = 0..3
__device__ float g_KP[4][BATCH * LSEQ];           // kp positions

// ---------------- helpers ----------------
__device__ __forceinline__ float warpSum(float v) {
    #pragma unroll
    for (int o = 16; o; o >>= 1) v += __shfl_xor_sync(0xffffffffu, v, o);
    return v;
}
__device__ __forceinline__ float warpMax(float v) {
    #pragma unroll
    for (int o = 16; o; o >>= 1) v = fmaxf(v, __shfl_xor_sync(0xffffffffu, v, o));
    return v;
}

// ---------------- positions ----------------
__global__ void pos_init_kernel(const int* __restrict__ qlen, const int* __restrict__ klen,
                                const float* __restrict__ psc, const float* __restrict__ pbi) {
    int b = blockIdx.x;
    int j = threadIdx.x;
    float scale = psc[0], bias = pbi[0];
    {
        int L = qlen[b];
        float Lf = (float)L;
        float step = (Lf > 1.0f) ? (Lf / (Lf - 1.0f)) : 0.0f;
        float pos = (-Lf * 0.5f + (float)j * step) * scale + bias;
        g_QP[0][b * LSEQ + j] = (j >= L) ? 10000.0f : pos;
    }
    {
        int L = klen[b];
        float Lf = (float)L;
        float step = (Lf > 1.0f) ? (Lf / (Lf - 1.0f)) : 0.0f;
        float pos = (-Lf * 0.5f + (float)j * step) * scale + bias;
        g_KP[0][b * LSEQ + j] = (j >= L) ? 10000.0f : pos;
    }
}

// per iteration t: compute d_t, write P_t = P_{t-1}*d_t, update qp (row direction)
__global__ void pos_row_kernel(int t) {
    int b = blockIdx.y;
    int w = threadIdx.x >> 5, lane = threadIdx.x & 31;
    int q = blockIdx.x * 8 + w;
    float qp = g_QP[t][b * LSEQ + q];
    bool qpad = (qp >= 1000.0f);
    const float* kpv = &g_KP[t][b * LSEQ];
    float* Pc = &g_P[t][((size_t)b * LSEQ + q) * LSEQ];
    const float* Pp = (t > 0) ? &g_P[t - 1][((size_t)b * LSEQ + q) * LSEQ] : (const float*)0;
    float sd = 0.f, sdk = 0.f;
    for (int k = lane; k < LSEQ; k += 32) {
        float kp = kpv[k];
        float df = qp - kp;
        float d = __expf(-0.5f * df * df);
        if (qpad || kp >= 1000.0f) d = 0.0f;
        Pc[k] = (t > 0) ? (Pp[k] * d) : d;
        sd += d;
        sdk += d * kp;
    }
    sd = warpSum(sd);
    sdk = warpSum(sdk);
    if (lane == 0) {
        float qn = sdk / fmaxf(sd, 1e-9f);
        g_QP[t + 1][b * LSEQ + q] = qpad ? 10000.0f : qn;
    }
}

// column direction: kp update from d_t (recomputed, cheap)
__global__ void pos_col_kernel(int t) {
    int b = blockIdx.y;
    int w = threadIdx.x >> 5, lane = threadIdx.x & 31;
    int k = blockIdx.x * 8 + w;
    float kp = g_KP[t][b * LSEQ + k];
    bool kpad = (kp >= 1000.0f);
    const float* qpv = &g_QP[t][b * LSEQ];
    float sd = 0.f, sdq = 0.f;
    for (int q = lane; q < LSEQ; q += 32) {
        float qp = qpv[q];
        float df = qp - kp;
        float d = __expf(-0.5f * df * df);
        if (kpad || qp >= 1000.0f) d = 0.0f;
        sd += d;
        sdq += d * qp;
    }
    sd = warpSum(sd);
    sdq = warpSum(sdq);
    if (lane == 0) {
        float kn = sdq / fmaxf(sd, 1e-9f);
        g_KP[t + 1][b * LSEQ + k] = kpad ? 10000.0f : kn;
    }
}

// ---------------- fp32 GEMM: C = A[M,K] @ W[N,K]^T + bias ----------------
// layout 0: C[m*N+n]   layout 1: split-heads QKV layout [B,H,L,DK]
__global__ void __launch_bounds__(256) sgemm128_kernel(
    const float* __restrict__ A, const float* __restrict__ W,
    const float* __restrict__ bias, float* __restrict__ C,
    int M, int N, int K, int layout)
{
    __shared__ float As[8][128];
    __shared__ float Bs[8][128];
    int tid = threadIdx.x;
    int bm = blockIdx.y * 128;
    int bn = blockIdx.x * 128;
    int lr = tid >> 1;
    int lk = (tid & 1) * 4;
    const float* Aload = A + (size_t)(bm + lr) * K + lk;
    const float* Bload = W + (size_t)(bn + lr) * K + lk;
    int ty = tid >> 4, tx = tid & 15;
    int r0 = ty * 8, c0 = tx * 8;
    float acc[8][8];
    #pragma unroll
    for (int i = 0; i < 8; i++)
        #pragma unroll
        for (int j = 0; j < 8; j++) acc[i][j] = 0.f;

    for (int k0 = 0; k0 < K; k0 += 8) {
        float4 av = *(const float4*)(Aload + k0);
        float4 bv = *(const float4*)(Bload + k0);
        As[lk + 0][lr] = av.x; As[lk + 1][lr] = av.y;
        As[lk + 2][lr] = av.z; As[lk + 3][lr] = av.w;
        Bs[lk + 0][lr] = bv.x; Bs[lk + 1][lr] = bv.y;
        Bs[lk + 2][lr] = bv.z; Bs[lk + 3][lr] = bv.w;
        __syncthreads();
        #pragma unroll
        for (int kk = 0; kk < 8; kk++) {
            float a[8], bb[8];
            *(float4*)&a[0]  = *(const float4*)&As[kk][r0];
            *(float4*)&a[4]  = *(const float4*)&As[kk][r0 + 4];
            *(float4*)&bb[0] = *(const float4*)&Bs[kk][c0];
            *(float4*)&bb[4] = *(const float4*)&Bs[kk][c0 + 4];
            #pragma unroll
            for (int i = 0; i < 8; i++)
                #pragma unroll
                for (int j = 0; j < 8; j++)
                    acc[i][j] += a[i] * bb[j];
        }
        __syncthreads();
    }

    #pragma unroll
    for (int i = 0; i < 8; i++) {
        int m = bm + r0 + i;
        #pragma unroll
        for (int j = 0; j < 8; j++) {
            int n = bn + c0 + j;
            float v = acc[i][j] + bias[n];
            if (layout == 0) {
                C[(size_t)m * N + n] = v;
            } else {
                int b = m >> 9, l = m & 511;
                int h = n >> 6, dk = n & 63;
                C[(((size_t)b * NH + h) * LSEQ + l) * DK + dk] = v;
            }
        }
    }
}

// ---------------- fused attention ----------------
// block = (b, 32-row q tile). loops all 16 heads:
//   scores -> weighted softmax with clip cascade (using P1,P2,P3) -> mean accum -> ctx
#define TQ 32
#define S_STRIDE 513
#define QT_STRIDE 36
#define KT_STRIDE 132
#define VT_STRIDE 68
#define SMEM_FLOATS (TQ * S_STRIDE + DK * QT_STRIDE + 8704 + 32)

__global__ void __launch_bounds__(256, 1) attn_kernel(float* __restrict__ out_mean) {
    extern __shared__ float sm[];
    float* S  = sm;                              // [32][513] scores -> e*P3 (scaled)
    float* QT = S + TQ * S_STRIDE;               // [64][36]  q transposed
    float* KVT = QT + DK * QT_STRIDE;            // K^T [64][132] or V [128][68]
    float* rowscale = KVT + 8704;                // [32]

    int b = blockIdx.y;
    int q0 = blockIdx.x * TQ;
    int tid = threadIdx.x;
    int lane = tid & 31;
    int warp = tid >> 5;

    float* meanp = out_mean + ((size_t)(b * LSEQ + q0)) * LSEQ;

    const float* P1 = &g_P[0][((size_t)b * LSEQ + q0) * LSEQ];
    const float* P2 = &g_P[1][((size_t)b * LSEQ + q0) * LSEQ];
    const float* P3 = &g_P[2][((size_t)b * LSEQ + q0) * LSEQ];

    for (int h = 0; h < NH; h++) {
        const float* Qg = g_Q + (((size_t)b * NH + h) * LSEQ + q0) * DK;
        const float* Kg = g_K + (((size_t)b * NH + h) * LSEQ) * DK;
        const float* Vg = g_V + (((size_t)b * NH + h) * LSEQ) * DK;

        // load Q tile transposed: QT[d][r]
        for (int idx = tid; idx < TQ * DK; idx += 256) {
            int r = idx >> 6, d = idx & 63;
            QT[d * QT_STRIDE + r] = Qg[idx];
        }

        // ---- scores over 4 k-chunks of 128 ----
        for (int kc = 0; kc < LSEQ; kc += 128) {
            for (int idx = tid; idx < 128 * DK; idx += 256) {
                int kk = idx >> 6, d = idx & 63;
                KVT[d * KT_STRIDE + kk] = Kg[(size_t)(kc) * DK + idx];
            }
            __syncthreads();
            int rg = tid >> 5;       // 0..7  (uniform in warp -> Q broadcast)
            int cg = tid & 31;       // 0..31
            int r0 = rg * 4, c0 = cg * 4;
            float acc[4][4];
            #pragma unroll
            for (int i = 0; i < 4; i++)
                #pragma unroll
                for (int j = 0; j < 4; j++) acc[i][j] = 0.f;
            #pragma unroll 4
            for (int d = 0; d < DK; d++) {
                float4 q4 = *(const float4*)(QT + d * QT_STRIDE + r0);
                float4 k4 = *(const float4*)(KVT + d * KT_STRIDE + c0);
                acc[0][0] += q4.x * k4.x; acc[0][1] += q4.x * k4.y; acc[0][2] += q4.x * k4.z; acc[0][3] += q4.x * k4.w;
                acc[1][0] += q4.y * k4.x; acc[1][1] += q4.y * k4.y; acc[1][2] += q4.y * k4.z; acc[1][3] += q4.y * k4.w;
                acc[2][0] += q4.z * k4.x; acc[2][1] += q4.z * k4.y; acc[2][2] += q4.z * k4.z; acc[2][3] += q4.z * k4.w;
                acc[3][0] += q4.w * k4.x; acc[3][1] += q4.w * k4.y; acc[3][2] += q4.w * k4.z; acc[3][3] += q4.w * k4.w;
            }
            #pragma unroll
            for (int i = 0; i < 4; i++)
                #pragma unroll
                for (int j = 0; j < 4; j++)
                    S[(r0 + i) * S_STRIDE + kc + c0 + j] = acc[i][j] * 0.125f;
            __syncthreads();
        }

        // ---- per-row: softmax max, exp, weighted sums with clip cascade ----
        #pragma unroll
        for (int i = 0; i < 4; i++) {
            int r = warp * 4 + i;
            float* Srow = S + r * S_STRIDE;
            const float* p1 = P1 + (size_t)r * LSEQ;
            const float* p2 = P2 + (size_t)r * LSEQ;
            const float* p3 = P3 + (size_t)r * LSEQ;
            float m = -1e30f;
            for (int k = lane; k < LSEQ; k += 32) m = fmaxf(m, Srow[k]);
            m = warpMax(m);
            float Z = 0.f, V1 = 0.f, V2 = 0.f, V3 = 0.f;
            for (int k = lane; k < LSEQ; k += 32) {
                float e = __expf(Srow[k] - m);
                float a = e * p3[k];
                Z  += e;
                V1 += e * p1[k];
                V2 += e * p2[k];
                V3 += a;
                Srow[k] = a;
            }
            Z = warpSum(Z); V1 = warpSum(V1); V2 = warpSum(V2); V3 = warpSum(V3);
            float u1 = V1 / Z;
            float c1 = fmaxf(u1, 1e-9f);
            float u2 = V2 / (Z * c1);
            float c2 = fmaxf(u2, 1e-9f);
            float u3 = V3 / (Z * c1 * c2);
            float c3 = fmaxf(u3, 1e-9f);
            if (lane == 0) rowscale[r] = 1.0f / (Z * c1 * c2 * c3);
        }
        __syncthreads();

        // ---- scale S in-place + accumulate head mean into output ----
        for (int idx = tid; idx < TQ * LSEQ; idx += 256) {
            int r = idx >> 9, k = idx & 511;
            float v = S[r * S_STRIDE + k] * rowscale[r];
            S[r * S_STRIDE + k] = v;
            float mv = v * (1.0f / (float)NH);
            if (h == 0) meanp[(size_t)r * LSEQ + k] = mv;
            else        meanp[(size_t)r * LSEQ + k] += mv;
        }

        // ---- ctx = attn @ V, 4 chunks of 128 k ----
        int rg2 = tid >> 4;          // 0..15
        int dg2 = tid & 15;          // 0..15
        int rr = rg2 * 2, d0 = dg2 * 4;
        float c00 = 0.f, c01 = 0.f, c02 = 0.f, c03 = 0.f;
        float c10 = 0.f, c11 = 0.f, c12 = 0.f, c13 = 0.f;
        for (int kc = 0; kc < LSEQ; kc += 128) {
            __syncthreads();
            for (int idx = tid; idx < 128 * DK; idx += 256) {
                int kk = idx >> 6, d = idx & 63;
                KVT[kk * VT_STRIDE + d] = Vg[(size_t)kc * DK + idx];
            }
            __syncthreads();
            #pragma unroll 4
            for (int kk = 0; kk < 128; kk++) {
                int k = kc + kk;
                float a0 = S[rr * S_STRIDE + k];
                float a1 = S[(rr + 1) * S_STRIDE + k];
                float4 v4 = *(const float4*)(KVT + kk * VT_STRIDE + d0);
                c00 += a0 * v4.x; c01 += a0 * v4.y; c02 += a0 * v4.z; c03 += a0 * v4.w;
                c10 += a1 * v4.x; c11 += a1 * v4.y; c12 += a1 * v4.z; c13 += a1 * v4.w;
            }
        }
        {
            size_t base0 = ((size_t)(b * LSEQ + q0 + rr)) * DMODEL + h * DK + d0;
            size_t base1 = base0 + DMODEL;
            g_CTX[base0 + 0] = c00; g_CTX[base0 + 1] = c01; g_CTX[base0 + 2] = c02; g_CTX[base0 + 3] = c03;
            g_CTX[base1 + 0] = c10; g_CTX[base1 + 1] = c11; g_CTX[base1 + 2] = c12; g_CTX[base1 + 3] = c13;
        }
        __syncthreads();
    }
}

// ---------------- host launch ----------------
extern "C" void kernel_launch(void* const* d_in, const int* in_sizes, int n_in,
                              void* d_out, int out_size) {
    const float* query = (const float*)d_in[0];
    const float* key   = (const float*)d_in[1];
    const float* value = (const float*)d_in[2];
    const int* qlen    = (const int*)d_in[3];
    const int* klen    = (const int*)d_in[4];
    const float* Wq = (const float*)d_in[5];
    const float* bq = (const float*)d_in[6];
    const float* Wk = (const float*)d_in[7];
    const float* bk = (const float*)d_in[8];
    const float* Wv = (const float*)d_in[9];
    const float* bv = (const float*)d_in[10];
    const float* Wo = (const float*)d_in[11];
    const float* bo = (const float*)d_in[12];
    const float* psc = (const float*)d_in[13];
    const float* pbi = (const float*)d_in[14];

    int B = in_sizes[3];          // batch (8)
    int M = B * LSEQ;             // 4096 rows

    float *pQ, *pK, *pV, *pCTX;
    cudaGetSymbolAddress((void**)&pQ, g_Q);
    cudaGetSymbolAddress((void**)&pK, g_K);
    cudaGetSymbolAddress((void**)&pV, g_V);
    cudaGetSymbolAddress((void**)&pCTX, g_CTX);

    // positions + distance-product precompute
    pos_init_kernel<<<B, LSEQ>>>(qlen, klen, psc, pbi);
    for (int t = 0; t < 3; t++) {
        pos_row_kernel<<<dim3(LSEQ / 8, B), 256>>>(t);
        pos_col_kernel<<<dim3(LSEQ / 8, B), 256>>>(t);
    }

    // Q/K/V projections
    dim3 gproj(DMODEL / 128, M / 128);
    sgemm128_kernel<<<gproj, 256>>>(query, Wq, bq, pQ, M, DMODEL, DMODEL, 1);
    sgemm128_kernel<<<gproj, 256>>>(key,   Wk, bk, pK, M, DMODEL, DMODEL, 1);
    sgemm128_kernel<<<gproj, 256>>>(value, Wv, bv, pV, M, DMODEL, DMODEL, 1);

    // fused attention (scores + clip-cascade softmax + mean + ctx)
    size_t smem_bytes = (size_t)SMEM_FLOATS * sizeof(float);
    cudaFuncSetAttribute(attn_kernel, cudaFuncAttributeMaxDynamicSharedMemorySize, (int)smem_bytes);
    float* out_mean = (float*)d_out + (size_t)M * DMODEL;
    attn_kernel<<<dim3(LSEQ / TQ, B), 256, smem_bytes>>>(out_mean);

    // output projection
    sgemm128_kernel<<<gproj, 256>>>(pCTX, Wo, bo, (float*)d_out, M, DMODEL, DMODEL, 0);
}

// round 3
// speedup vs baseline: 1.4499x; 1.4499x over previous
#include <cuda_runtime.h>
#include <cuda_bf16.h>
#include <math.h>
#include <stdint.h>

#define BATCH 8
#define LSEQ 512
#define DMODEL 1024
#define NH 16
#define DK 64

// ---------------- scratch (static device memory; no allocations) ----------------
__device__ float g_Q[BATCH * NH * LSEQ * DK];     // [B,H,L,DK]
__device__ float g_K[BATCH * NH * LSEQ * DK];
__device__ float g_V[BATCH * NH * LSEQ * DK];
__device__ float g_CTX[BATCH * LSEQ * DMODEL];    // [B*L, D] heads merged
__device__ float g_P[3][BATCH * LSEQ * LSEQ];     // cumulative distance products P1,P2,P3
__device__ float g_QP[4][BATCH * LSEQ];
__device__ float g_KP[4][BATCH * LSEQ];

// ---------------- generic helpers ----------------
__device__ __forceinline__ float warpSum(float v) {
    #pragma unroll
    for (int o = 16; o; o >>= 1) v += __shfl_xor_sync(0xffffffffu, v, o);
    return v;
}
__device__ __forceinline__ float warpMax(float v) {
    #pragma unroll
    for (int o = 16; o; o >>= 1) v = fmaxf(v, __shfl_xor_sync(0xffffffffu, v, o));
    return v;
}
__device__ __forceinline__ uint32_t smem_u32(const void* p) {
    uint32_t a;
    asm("{ .reg .u64 t; cvta.to.shared.u64 t, %1; cvt.u32.u64 %0, t; }" : "=r"(a) : "l"(p));
    return a;
}

// ---------------- HMMA helpers (mma.sync, baseline PTX — works at compute_103) ---
__device__ __forceinline__ void ldsm4(uint32_t* r, uint32_t addr) {
    asm volatile("ldmatrix.sync.aligned.m8n8.x4.shared.b16 {%0,%1,%2,%3}, [%4];"
                 : "=r"(r[0]), "=r"(r[1]), "=r"(r[2]), "=r"(r[3]) : "r"(addr));
}
__device__ __forceinline__ void mma16816(float* c, const uint32_t* a, uint32_t b0, uint32_t b1) {
    asm volatile("mma.sync.aligned.m16n8k16.row.col.f32.bf16.bf16.f32 "
                 "{%0,%1,%2,%3}, {%4,%5,%6,%7}, {%8,%9}, {%10,%11,%12,%13};"
                 : "=f"(c[0]), "=f"(c[1]), "=f"(c[2]), "=f"(c[3])
                 : "r"(a[0]), "r"(a[1]), "r"(a[2]), "r"(a[3]),
                   "r"(b0), "r"(b1),
                   "f"(c[0]), "f"(c[1]), "f"(c[2]), "f"(c[3]));
}
__device__ __forceinline__ uint32_t packbf2(float x, float y) {
    __nv_bfloat162 h = __floats2bfloat162_rn(x, y);
    return *(uint32_t*)&h;
}
// split a float4 into hi/lo bf16x2 pairs
__device__ __forceinline__ void split4(float4 x, uint2& hi, uint2& lo) {
    uint32_t h0 = packbf2(x.x, x.y);
    uint32_t h1 = packbf2(x.z, x.w);
    float bx = __uint_as_float(h0 << 16);
    float by = __uint_as_float(h0 & 0xffff0000u);
    float bz = __uint_as_float(h1 << 16);
    float bw = __uint_as_float(h1 & 0xffff0000u);
    hi = make_uint2(h0, h1);
    lo = make_uint2(packbf2(x.x - bx, x.y - by), packbf2(x.z - bz, x.w - bw));
}

// ---------------- positions ----------------
__global__ void pos_init_kernel(const int* __restrict__ qlen, const int* __restrict__ klen,
                                const float* __restrict__ psc, const float* __restrict__ pbi) {
    int b = blockIdx.x;
    int j = threadIdx.x;
    float scale = psc[0], bias = pbi[0];
    {
        int L = qlen[b];
        float Lf = (float)L;
        float step = (Lf > 1.0f) ? (Lf / (Lf - 1.0f)) : 0.0f;
        float pos = (-Lf * 0.5f + (float)j * step) * scale + bias;
        g_QP[0][b * LSEQ + j] = (j >= L) ? 10000.0f : pos;
    }
    {
        int L = klen[b];
        float Lf = (float)L;
        float step = (Lf > 1.0f) ? (Lf / (Lf - 1.0f)) : 0.0f;
        float pos = (-Lf * 0.5f + (float)j * step) * scale + bias;
        g_KP[0][b * LSEQ + j] = (j >= L) ? 10000.0f : pos;
    }
}

__global__ void pos_row_kernel(int t) {
    int b = blockIdx.y;
    int w = threadIdx.x >> 5, lane = threadIdx.x & 31;
    int q = blockIdx.x * 8 + w;
    float qp = g_QP[t][b * LSEQ + q];
    bool qpad = (qp >= 1000.0f);
    const float* kpv = &g_KP[t][b * LSEQ];
    float* Pc = &g_P[t][((size_t)b * LSEQ + q) * LSEQ];
    const float* Pp = (t > 0) ? &g_P[t - 1][((size_t)b * LSEQ + q) * LSEQ] : (const float*)0;
    float sd = 0.f, sdk = 0.f;
    for (int k = lane; k < LSEQ; k += 32) {
        float kp = kpv[k];
        float df = qp - kp;
        float d = __expf(-0.5f * df * df);
        if (qpad || kp >= 1000.0f) d = 0.0f;
        Pc[k] = (t > 0) ? (Pp[k] * d) : d;
        sd += d;
        sdk += d * kp;
    }
    sd = warpSum(sd);
    sdk = warpSum(sdk);
    if (lane == 0) {
        float qn = sdk / fmaxf(sd, 1e-9f);
        g_QP[t + 1][b * LSEQ + q] = qpad ? 10000.0f : qn;
    }
}

__global__ void pos_col_kernel(int t) {
    int b = blockIdx.y;
    int w = threadIdx.x >> 5, lane = threadIdx.x & 31;
    int k = blockIdx.x * 8 + w;
    float kp = g_KP[t][b * LSEQ + k];
    bool kpad = (kp >= 1000.0f);
    const float* qpv = &g_QP[t][b * LSEQ];
    float sd = 0.f, sdq = 0.f;
    for (int q = lane; q < LSEQ; q += 32) {
        float qp = qpv[q];
        float df = qp - kp;
        float d = __expf(-0.5f * df * df);
        if (kpad || qp >= 1000.0f) d = 0.0f;
        sd += d;
        sdq += d * qp;
    }
    sd = warpSum(sd);
    sdq = warpSum(sdq);
    if (lane == 0) {
        float kn = sdq / fmaxf(sd, 1e-9f);
        g_KP[t + 1][b * LSEQ + k] = kpad ? 10000.0f : kn;
    }
}

// ---------------- HMMA bf16-split GEMM ----------------
// C[4096,1024] = A[4096,1024] @ W[1024,1024]^T + bias, via Ah*Bh + Ah*Bl + Al*Bh.
// CTA tile 128x128, 4 warps (warp tile 64x64), chunk K=16 fp32, double-buffered.
// Regions per stage (padded rows, 48B stride, 16 bf16 cols): Ah, Al, Bh, Bl.
#define RSTRIDE 48
#define RGN (128 * RSTRIDE)          // 6144 B
#define STG (4 * RGN)                // 24576 B
#define GEMM_SMEM (2 * STG)          // 49152 B
#define NCHUNK 64

__global__ void __launch_bounds__(128, 2) hmma_gemm_kernel(
    const float* __restrict__ A, const float* __restrict__ W,
    const float* __restrict__ bias, float* __restrict__ C, int layout)
{
    extern __shared__ char smc[];
    uint32_t sb = smem_u32(smc);
    int tid = threadIdx.x, lane = tid & 31, wid = tid >> 5;
    int bm = blockIdx.y * 128, bn = blockIdx.x * 128;
    int wM = (wid & 1) * 64, wN = (wid >> 1) * 64;

    float acc[4][8][4];
    #pragma unroll
    for (int i = 0; i < 4; i++)
        #pragma unroll
        for (int j = 0; j < 8; j++)
            #pragma unroll
            for (int k = 0; k < 4; k++) acc[i][j][k] = 0.f;

    // ldg/sts mapping: thread covers rows r0 + {0,32,64,96}, float4 col c4
    int r0 = tid >> 2;
    int c4 = tid & 3;
    const float* Ag = A + (size_t)(bm + r0) * 1024 + c4 * 4;
    const float* Wg = W + (size_t)(bn + r0) * 1024 + c4 * 4;
    uint32_t sts = (uint32_t)(r0 * RSTRIDE + c4 * 8);

    // ldmatrix per-lane offset within a region
    uint32_t frow = (uint32_t)((lane & 15) * RSTRIDE + ((lane >> 4) << 4));

    float4 av[4], wv[4];

    // ---- preload chunk 0 into stage 0 ----
    #pragma unroll
    for (int i = 0; i < 4; i++) {
        av[i] = *(const float4*)(Ag + (size_t)(i * 32) * 1024);
        wv[i] = *(const float4*)(Wg + (size_t)(i * 32) * 1024);
    }
    #pragma unroll
    for (int i = 0; i < 4; i++) {
        uint2 hi, lo;
        uint32_t o = sts + i * 32 * RSTRIDE;
        split4(av[i], hi, lo);
        *(uint2*)(smc + 0 * RGN + o) = hi;
        *(uint2*)(smc + 1 * RGN + o) = lo;
        split4(wv[i], hi, lo);
        *(uint2*)(smc + 2 * RGN + o) = hi;
        *(uint2*)(smc + 3 * RGN + o) = lo;
    }
    __syncthreads();

    for (int c = 0; c < NCHUNK; c++) {
        uint32_t stage = sb + (uint32_t)(c & 1) * STG;
        if (c < NCHUNK - 1) {
            int cc = (c + 1) * 16;
            #pragma unroll
            for (int i = 0; i < 4; i++) {
                av[i] = *(const float4*)(Ag + (size_t)(i * 32) * 1024 + cc);
                wv[i] = *(const float4*)(Wg + (size_t)(i * 32) * 1024 + cc);
            }
        }

        // ---- compute on stage ----
        uint32_t Ah = stage, Al = stage + RGN, Bh = stage + 2 * RGN, Bl = stage + 3 * RGN;
        uint32_t a[4][4], bh[4][4], bl[4][4];
        #pragma unroll
        for (int mi = 0; mi < 4; mi++)
            ldsm4(a[mi], Ah + (uint32_t)((wM + mi * 16) * RSTRIDE) + frow);
        #pragma unroll
        for (int bj = 0; bj < 4; bj++)
            ldsm4(bh[bj], Bh + (uint32_t)((wN + bj * 16) * RSTRIDE) + frow);
        #pragma unroll
        for (int mi = 0; mi < 4; mi++)
            #pragma unroll
            for (int bj = 0; bj < 4; bj++) {
                mma16816(acc[mi][2 * bj + 0], a[mi], bh[bj][0], bh[bj][2]);
                mma16816(acc[mi][2 * bj + 1], a[mi], bh[bj][1], bh[bj][3]);
            }
        #pragma unroll
        for (int bj = 0; bj < 4; bj++)
            ldsm4(bl[bj], Bl + (uint32_t)((wN + bj * 16) * RSTRIDE) + frow);
        #pragma unroll
        for (int mi = 0; mi < 4; mi++)
            #pragma unroll
            for (int bj = 0; bj < 4; bj++) {
                mma16816(acc[mi][2 * bj + 0], a[mi], bl[bj][0], bl[bj][2]);
                mma16816(acc[mi][2 * bj + 1], a[mi], bl[bj][1], bl[bj][3]);
            }
        #pragma unroll
        for (int mi = 0; mi < 4; mi++)
            ldsm4(a[mi], Al + (uint32_t)((wM + mi * 16) * RSTRIDE) + frow);
        #pragma unroll
        for (int mi = 0; mi < 4; mi++)
            #pragma unroll
            for (int bj = 0; bj < 4; bj++) {
                mma16816(acc[mi][2 * bj + 0], a[mi], bh[bj][0], bh[bj][2]);
                mma16816(acc[mi][2 * bj + 1], a[mi], bh[bj][1], bh[bj][3]);
            }

        // ---- store next chunk into other stage ----
        if (c < NCHUNK - 1) {
            char* nst = smc + ((c + 1) & 1) * STG;
            #pragma unroll
            for (int i = 0; i < 4; i++) {
                uint2 hi, lo;
                uint32_t o = sts + i * 32 * RSTRIDE;
                split4(av[i], hi, lo);
                *(uint2*)(nst + 0 * RGN + o) = hi;
                *(uint2*)(nst + 1 * RGN + o) = lo;
                split4(wv[i], hi, lo);
                *(uint2*)(nst + 2 * RGN + o) = hi;
                *(uint2*)(nst + 3 * RGN + o) = lo;
            }
        }
        __syncthreads();
    }

    // ---- epilogue ----
    int g = lane >> 2, tg = lane & 3;
    #pragma unroll
    for (int mi = 0; mi < 4; mi++) {
        int m0 = bm + wM + mi * 16 + g;
        #pragma unroll
        for (int nj = 0; nj < 8; nj++) {
            int n = bn + wN + nj * 8 + tg * 2;
            float2 bz = *(const float2*)(bias + n);
            float2 v0 = make_float2(acc[mi][nj][0] + bz.x, acc[mi][nj][1] + bz.y);
            float2 v1 = make_float2(acc[mi][nj][2] + bz.x, acc[mi][nj][3] + bz.y);
            if (layout == 0) {
                *(float2*)(C + (size_t)m0 * 1024 + n) = v0;
                *(float2*)(C + (size_t)(m0 + 8) * 1024 + n) = v1;
            } else {
                int h = n >> 6, dk = n & 63;
                int b0 = m0 >> 9, l0 = m0 & 511;
                int b1 = (m0 + 8) >> 9, l1 = (m0 + 8) & 511;
                *(float2*)(C + (((size_t)(b0 * NH + h) * LSEQ) + l0) * DK + dk) = v0;
                *(float2*)(C + (((size_t)(b1 * NH + h) * LSEQ) + l1) * DK + dk) = v1;
            }
        }
    }
}

// ---------------- fused attention ----------------
#define TQ 32
#define S_STRIDE 513
#define QT_STRIDE 36
#define KT_STRIDE 132
#define VT_STRIDE 68
#define SMEM_FLOATS (TQ * S_STRIDE + DK * QT_STRIDE + 8704 + 32)

__global__ void __launch_bounds__(256, 1) attn_kernel(float* __restrict__ out_mean) {
    extern __shared__ float sm[];
    float* S  = sm;
    float* QT = S + TQ * S_STRIDE;
    float* KVT = QT + DK * QT_STRIDE;
    float* rowscale = KVT + 8704;

    int b = blockIdx.y;
    int q0 = blockIdx.x * TQ;
    int tid = threadIdx.x;
    int lane = tid & 31;
    int warp = tid >> 5;

    float* meanp = out_mean + ((size_t)(b * LSEQ + q0)) * LSEQ;

    const float* P1 = &g_P[0][((size_t)b * LSEQ + q0) * LSEQ];
    const float* P2 = &g_P[1][((size_t)b * LSEQ + q0) * LSEQ];
    const float* P3 = &g_P[2][((size_t)b * LSEQ + q0) * LSEQ];

    for (int h = 0; h < NH; h++) {
        const float* Qg = g_Q + (((size_t)b * NH + h) * LSEQ + q0) * DK;
        const float* Kg = g_K + (((size_t)b * NH + h) * LSEQ) * DK;
        const float* Vg = g_V + (((size_t)b * NH + h) * LSEQ) * DK;

        for (int idx = tid; idx < TQ * DK; idx += 256) {
            int r = idx >> 6, d = idx & 63;
            QT[d * QT_STRIDE + r] = Qg[idx];
        }

        for (int kc = 0; kc < LSEQ; kc += 128) {
            for (int idx = tid; idx < 128 * DK; idx += 256) {
                int kk = idx >> 6, d = idx & 63;
                KVT[d * KT_STRIDE + kk] = Kg[(size_t)(kc) * DK + idx];
            }
            __syncthreads();
            int rg = tid >> 5;
            int cg = tid & 31;
            int r0 = rg * 4, c0 = cg * 4;
            float acc[4][4];
            #pragma unroll
            for (int i = 0; i < 4; i++)
                #pragma unroll
                for (int j = 0; j < 4; j++) acc[i][j] = 0.f;
            #pragma unroll 4
            for (int d = 0; d < DK; d++) {
                float4 q4 = *(const float4*)(QT + d * QT_STRIDE + r0);
                float4 k4 = *(const float4*)(KVT + d * KT_STRIDE + c0);
                acc[0][0] += q4.x * k4.x; acc[0][1] += q4.x * k4.y; acc[0][2] += q4.x * k4.z; acc[0][3] += q4.x * k4.w;
                acc[1][0] += q4.y * k4.x; acc[1][1] += q4.y * k4.y; acc[1][2] += q4.y * k4.z; acc[1][3] += q4.y * k4.w;
                acc[2][0] += q4.z * k4.x; acc[2][1] += q4.z * k4.y; acc[2][2] += q4.z * k4.z; acc[2][3] += q4.z * k4.w;
                acc[3][0] += q4.w * k4.x; acc[3][1] += q4.w * k4.y; acc[3][2] += q4.w * k4.z; acc[3][3] += q4.w * k4.w;
            }
            #pragma unroll
            for (int i = 0; i < 4; i++)
                #pragma unroll
                for (int j = 0; j < 4; j++)
                    S[(r0 + i) * S_STRIDE + kc + c0 + j] = acc[i][j] * 0.125f;
            __syncthreads();
        }

        #pragma unroll
        for (int i = 0; i < 4; i++) {
            int r = warp * 4 + i;
            float* Srow = S + r * S_STRIDE;
            const float* p1 = P1 + (size_t)r * LSEQ;
            const float* p2 = P2 + (size_t)r * LSEQ;
            const float* p3 = P3 + (size_t)r * LSEQ;
            float m = -1e30f;
            for (int k = lane; k < LSEQ; k += 32) m = fmaxf(m, Srow[k]);
            m = warpMax(m);
            float Z = 0.f, V1 = 0.f, V2 = 0.f, V3 = 0.f;
            for (int k = lane; k < LSEQ; k += 32) {
                float e = __expf(Srow[k] - m);
                float a = e * p3[k];
                Z  += e;
                V1 += e * p1[k];
                V2 += e * p2[k];
                V3 += a;
                Srow[k] = a;
            }
            Z = warpSum(Z); V1 = warpSum(V1); V2 = warpSum(V2); V3 = warpSum(V3);
            float u1 = V1 / Z;
            float c1 = fmaxf(u1, 1e-9f);
            float u2 = V2 / (Z * c1);
            float c2 = fmaxf(u2, 1e-9f);
            float u3 = V3 / (Z * c1 * c2);
            float c3 = fmaxf(u3, 1e-9f);
            if (lane == 0) rowscale[r] = 1.0f / (Z * c1 * c2 * c3);
        }
        __syncthreads();

        for (int idx = tid; idx < TQ * LSEQ; idx += 256) {
            int r = idx >> 9, k = idx & 511;
            float v = S[r * S_STRIDE + k] * rowscale[r];
            S[r * S_STRIDE + k] = v;
            float mv = v * (1.0f / (float)NH);
            if (h == 0) meanp[(size_t)r * LSEQ + k] = mv;
            else        meanp[(size_t)r * LSEQ + k] += mv;
        }

        int rg2 = tid >> 4;
        int dg2 = tid & 15;
        int rr = rg2 * 2, d0 = dg2 * 4;
        float c00 = 0.f, c01 = 0.f, c02 = 0.f, c03 = 0.f;
        float c10 = 0.f, c11 = 0.f, c12 = 0.f, c13 = 0.f;
        for (int kc = 0; kc < LSEQ; kc += 128) {
            __syncthreads();
            for (int idx = tid; idx < 128 * DK; idx += 256) {
                int kk = idx >> 6, d = idx & 63;
                KVT[kk * VT_STRIDE + d] = Vg[(size_t)kc * DK + idx];
            }
            __syncthreads();
            #pragma unroll 4
            for (int kk = 0; kk < 128; kk++) {
                int k = kc + kk;
                float a0 = S[rr * S_STRIDE + k];
                float a1 = S[(rr + 1) * S_STRIDE + k];
                float4 v4 = *(const float4*)(KVT + kk * VT_STRIDE + d0);
                c00 += a0 * v4.x; c01 += a0 * v4.y; c02 += a0 * v4.z; c03 += a0 * v4.w;
                c10 += a1 * v4.x; c11 += a1 * v4.y; c12 += a1 * v4.z; c13 += a1 * v4.w;
            }
        }
        {
            size_t base0 = ((size_t)(b * LSEQ + q0 + rr)) * DMODEL + h * DK + d0;
            size_t base1 = base0 + DMODEL;
            g_CTX[base0 + 0] = c00; g_CTX[base0 + 1] = c01; g_CTX[base0 + 2] = c02; g_CTX[base0 + 3] = c03;
            g_CTX[base1 + 0] = c10; g_CTX[base1 + 1] = c11; g_CTX[base1 + 2] = c12; g_CTX[base1 + 3] = c13;
        }
        __syncthreads();
    }
}

// ---------------- host launch ----------------
extern "C" void kernel_launch(void* const* d_in, const int* in_sizes, int n_in,
                              void* d_out, int out_size) {
    const float* query = (const float*)d_in[0];
    const float* key   = (const float*)d_in[1];
    const float* value = (const float*)d_in[2];
    const int* qlen    = (const int*)d_in[3];
    const int* klen    = (const int*)d_in[4];
    const float* Wq = (const float*)d_in[5];
    const float* bq = (const float*)d_in[6];
    const float* Wk = (const float*)d_in[7];
    const float* bk = (const float*)d_in[8];
    const float* Wv = (const float*)d_in[9];
    const float* bv = (const float*)d_in[10];
    const float* Wo = (const float*)d_in[11];
    const float* bo = (const float*)d_in[12];
    const float* psc = (const float*)d_in[13];
    const float* pbi = (const float*)d_in[14];

    int B = in_sizes[3];
    int M = B * LSEQ;

    float *pQ, *pK, *pV, *pCTX;
    cudaGetSymbolAddress((void**)&pQ, g_Q);
    cudaGetSymbolAddress((void**)&pK, g_K);
    cudaGetSymbolAddress((void**)&pV, g_V);
    cudaGetSymbolAddress((void**)&pCTX, g_CTX);

    // positions + distance-product precompute
    pos_init_kernel<<<B, LSEQ>>>(qlen, klen, psc, pbi);
    for (int t = 0; t < 3; t++) {
        pos_row_kernel<<<dim3(LSEQ / 8, B), 256>>>(t);
        pos_col_kernel<<<dim3(LSEQ / 8, B), 256>>>(t);
    }

    // HMMA bf16-split projections
    cudaFuncSetAttribute(hmma_gemm_kernel, cudaFuncAttributeMaxDynamicSharedMemorySize, GEMM_SMEM);
    dim3 ggemm(DMODEL / 128, M / 128);
    hmma_gemm_kernel<<<ggemm, 128, GEMM_SMEM>>>(query, Wq, bq, pQ, 1);
    hmma_gemm_kernel<<<ggemm, 128, GEMM_SMEM>>>(key,   Wk, bk, pK, 1);
    hmma_gemm_kernel<<<ggemm, 128, GEMM_SMEM>>>(value, Wv, bv, pV, 1);

    // fused attention
    size_t smem_bytes = (size_t)SMEM_FLOATS * sizeof(float);
    cudaFuncSetAttribute(attn_kernel, cudaFuncAttributeMaxDynamicSharedMemorySize, (int)smem_bytes);
    float* out_mean = (float*)d_out + (size_t)M * DMODEL;
    attn_kernel<<<dim3(LSEQ / TQ, B), 256, smem_bytes>>>(out_mean);

    // output projection
    hmma_gemm_kernel<<<ggemm, 128, GEMM_SMEM>>>(pCTX, Wo, bo, (float*)d_out, 0);
}